// round 9
// baseline (speedup 1.0000x reference)
#include <cuda_runtime.h>
#include <cuda_bf16.h>
#include <math.h>

// Problem constants
#define BB 64
#define TT 1024
#define QD 1024
#define CD 512
#define SPLITS 16
#define TCHUNK (TT / SPLITS)   // 64

// Output layout (float32): context[B,CD] | a[B,T] | u_new[B] | sq_new[B]
#define CTX_OFF 0
#define A_OFF   (BB * CD)                 // 32768
#define U_OFF   (A_OFF + BB * TT)         // 98304
#define SQ_OFF  (U_OFF + BB)              // 98368

// Scratch
__device__ float        g_partial[BB * SPLITS * CD]; // unnormalized partial contexts
__device__ float        g_hdot[BB * SPLITS * 2];     // per-chunk head-dot partials
__device__ unsigned int g_cnt[BB];                   // per-batch producer count
__device__ unsigned int g_done[BB];                  // per-batch consumer count

__device__ __forceinline__ float alpha_v(
    const float* __restrict__ arow, int t, float ub, float sqb)
{
    const float cur  = arow[t];
    const float prev = (t > 0) ? arow[t - 1] : 0.0f;
    const float base = fmaf(-ub, cur, cur) + fmaf(ub, prev, 1e-6f);
    return __expf(sqb * __logf(base));   // base > 0 always
}

// ---------------------------------------------------------------------------
// K2: fused alpha + split-T partial context + head-dot partials.
// Grid (SPLITS, B), 128 threads. PDL trigger at START so k_finish co-resides.
// Publishes completion per batch via release-RED (no full threadfence).
// ---------------------------------------------------------------------------
__global__ void __launch_bounds__(128) k_context_partial(
    const float* __restrict__ inputs,
    const float* __restrict__ alpha,
    const float* __restrict__ u,
    const float* __restrict__ sq,
    const float* __restrict__ W_u,
    const float* __restrict__ W_sq,
    float* __restrict__ partial,
    float* __restrict__ hdot,
    unsigned int* __restrict__ cnt)
{
#if __CUDA_ARCH__ >= 900
    cudaTriggerProgrammaticLaunchCompletion();
#endif
    const int s   = blockIdx.x;
    const int b   = blockIdx.y;
    const int tid = threadIdx.x;
    const int t0  = s * TCHUNK;

    __shared__ float sa[TCHUNK];

    if (tid < TCHUNK) {
        const float ub  = u[b];
        const float sqb = sq[b];
        sa[tid] = alpha_v(alpha + (size_t)b * TT, t0 + tid, ub, sqb);
    }
    __syncthreads();

    const float4* __restrict__ inp =
        (const float4*)(inputs + ((size_t)b * TT + t0) * CD) + tid;

    float4 a0 = {0,0,0,0}, a1 = {0,0,0,0}, a2 = {0,0,0,0}, a3 = {0,0,0,0};
    #pragma unroll 4
    for (int i = 0; i < TCHUNK; i += 4) {
        const float4 v0 = __ldcs(&inp[(size_t)(i + 0) * (CD/4)]);
        const float4 v1 = __ldcs(&inp[(size_t)(i + 1) * (CD/4)]);
        const float4 v2 = __ldcs(&inp[(size_t)(i + 2) * (CD/4)]);
        const float4 v3 = __ldcs(&inp[(size_t)(i + 3) * (CD/4)]);
        const float w0 = sa[i + 0], w1 = sa[i + 1], w2 = sa[i + 2], w3 = sa[i + 3];
        a0.x = fmaf(w0, v0.x, a0.x); a0.y = fmaf(w0, v0.y, a0.y);
        a0.z = fmaf(w0, v0.z, a0.z); a0.w = fmaf(w0, v0.w, a0.w);
        a1.x = fmaf(w1, v1.x, a1.x); a1.y = fmaf(w1, v1.y, a1.y);
        a1.z = fmaf(w1, v1.z, a1.z); a1.w = fmaf(w1, v1.w, a1.w);
        a2.x = fmaf(w2, v2.x, a2.x); a2.y = fmaf(w2, v2.y, a2.y);
        a2.z = fmaf(w2, v2.z, a2.z); a2.w = fmaf(w2, v2.w, a2.w);
        a3.x = fmaf(w3, v3.x, a3.x); a3.y = fmaf(w3, v3.y, a3.y);
        a3.z = fmaf(w3, v3.z, a3.z); a3.w = fmaf(w3, v3.w, a3.w);
    }
    float4 r;
    r.x = (a0.x + a1.x) + (a2.x + a3.x);
    r.y = (a0.y + a1.y) + (a2.y + a3.y);
    r.z = (a0.z + a1.z) + (a2.z + a3.z);
    r.w = (a0.w + a1.w) + (a2.w + a3.w);
    ((float4*)(partial + ((size_t)b * SPLITS + s) * CD))[tid] = r;

    // head-dot partials vs W_u/W_sq context rows (cols 0..511)
    const float4 wu = ((const float4*)W_u)[tid];
    const float4 ws = ((const float4*)W_sq)[tid];
    float hu = r.x * wu.x + r.y * wu.y + r.z * wu.z + r.w * wu.w;
    float hs = r.x * ws.x + r.y * ws.y + r.z * ws.z + r.w * ws.w;
    #pragma unroll
    for (int o = 16; o > 0; o >>= 1) {
        hu += __shfl_xor_sync(0xffffffffu, hu, o);
        hs += __shfl_xor_sync(0xffffffffu, hs, o);
    }
    __shared__ float ru[4], rs[4];
    if ((tid & 31) == 0) { ru[tid >> 5] = hu; rs[tid >> 5] = hs; }
    __syncthreads();
    if (tid == 0) {
        hdot[((size_t)b * SPLITS + s) * 2 + 0] = (ru[0] + ru[1]) + (ru[2] + ru[3]);
        hdot[((size_t)b * SPLITS + s) * 2 + 1] = (rs[0] + rs[1]) + (rs[2] + rs[3]);
        // release-publish this block's writes for batch b
        asm volatile("red.release.gpu.global.add.u32 [%0], %1;"
                     :: "l"(cnt + b), "r"(1u) : "memory");
    }
}

// Spin until all SPLITS producers of batch b have released. tid 0 only.
__device__ __forceinline__ void wait_batch(
    unsigned int* __restrict__ cnt, unsigned int* __restrict__ done, int b, int tid)
{
    if (tid == 0) {
        unsigned int v;
        do {
            asm volatile("ld.acquire.gpu.global.u32 %0, [%1];"
                         : "=r"(v) : "l"(cnt + b) : "memory");
            if (v < SPLITS) __nanosleep(64);
        } while (v < SPLITS);
        // replay-safe reset: 5 waiting roles per batch; last one resets both.
        const unsigned int old = atomicAdd(done + b, 1u);
        if (old == 4u) { cnt[b] = 0u; done[b] = 0u; }
    }
    __syncthreads();
}

// ---------------------------------------------------------------------------
// K3 (PDL secondary, co-resident): grid (6, B), 128 threads.
// role 4    : input-only (normalized 'a'), never waits.
// roles 0..3: wait for batch b, reduce a 128-column slab.
// role 5    : precompute query-dot, wait, finish heads.
// ---------------------------------------------------------------------------
__global__ void __launch_bounds__(128) k_finish(
    const float* __restrict__ partial,
    const float* __restrict__ hdot,
    const float* __restrict__ alpha,
    const float* __restrict__ u,
    const float* __restrict__ sq,
    const float* __restrict__ query,
    const float* __restrict__ W_u,  const float* __restrict__ b_u,
    const float* __restrict__ W_sq, const float* __restrict__ b_sq,
    float* __restrict__ out,
    unsigned int* __restrict__ cnt,
    unsigned int* __restrict__ done)
{
    const int role = blockIdx.x;
    const int b    = blockIdx.y;
    const int tid  = threadIdx.x;

    __shared__ float red[4];

    // S from inputs only (overlaps K2)
    const float ub  = u[b];
    const float sqb = sq[b];
    const float* arow = alpha + (size_t)b * TT;
    float sacc = 0.0f;
    #pragma unroll
    for (int t = tid; t < TT; t += 128) sacc += alpha_v(arow, t, ub, sqb);
    #pragma unroll
    for (int o = 16; o > 0; o >>= 1) sacc += __shfl_xor_sync(0xffffffffu, sacc, o);
    if ((tid & 31) == 0) red[tid >> 5] = sacc;
    __syncthreads();
    const float S   = (red[0] + red[1]) + (red[2] + red[3]);
    const float inv = 1.0f / S;

    if (role == 4) {
        // normalized 'a' — input-only, no wait.
        #pragma unroll
        for (int t = tid; t < TT; t += 128)
            out[A_OFF + (size_t)b * TT + t] = alpha_v(arow, t, ub, sqb) * inv;
        return;
    }

    if (role == 5) {
        // pre-wait: query-part dot (independent of K2)
        const float4* __restrict__ q4 = (const float4*)(query + (size_t)b * QD);
        float pu = 0.0f, ps = 0.0f;
        #pragma unroll
        for (int j = 0; j < 2; j++) {
            const int i = j * 128 + tid;
            const float4 q  = q4[i];
            const float4 wu = ((const float4*)(W_u  + CD))[i];
            const float4 ws = ((const float4*)(W_sq + CD))[i];
            pu += q.x * wu.x + q.y * wu.y + q.z * wu.z + q.w * wu.w;
            ps += q.x * ws.x + q.y * ws.y + q.z * ws.z + q.w * ws.w;
        }
        #pragma unroll
        for (int o = 16; o > 0; o >>= 1) {
            pu += __shfl_xor_sync(0xffffffffu, pu, o);
            ps += __shfl_xor_sync(0xffffffffu, ps, o);
        }
        __shared__ float ru[4], rs[4];
        if ((tid & 31) == 0) { ru[tid >> 5] = pu; rs[tid >> 5] = ps; }
        __syncthreads();

        wait_batch(cnt, done, b, tid);

        if (tid == 0) {
            float hu = 0.0f, hs = 0.0f;
            #pragma unroll
            for (int k = 0; k < SPLITS; k++) {
                hu += hdot[((size_t)b * SPLITS + k) * 2 + 0];
                hs += hdot[((size_t)b * SPLITS + k) * 2 + 1];
            }
            const float PU = hu * inv + (ru[0] + ru[1]) + (ru[2] + ru[3]) + b_u[0];
            const float PS = hs * inv + (rs[0] + rs[1]) + (rs[2] + rs[3]) + b_sq[0];
            out[U_OFF + b]  = 1.0f / (1.0f + expf(-PU));
            out[SQ_OFF + b] = 1.0f / (1.0f + expf(-PS)) + 1.0f;
        }
        return;
    }

    // roles 0..3: reduce a 128-column slab of the partials.
    wait_batch(cnt, done, b, tid);

    const int g  = (tid & 31) + role * 32;          // float4 group in [0,128)
    const int k0 = (tid >> 5) * (SPLITS / 4);
    const float4* __restrict__ p4 =
        (const float4*)(partial + (size_t)b * SPLITS * CD);
    float4 acc = {0,0,0,0};
    #pragma unroll
    for (int k = 0; k < SPLITS / 4; k++) {
        const float4 v = p4[(size_t)(k0 + k) * (CD/4) + g];
        acc.x += v.x; acc.y += v.y; acc.z += v.z; acc.w += v.w;
    }
    __shared__ float4 tmp[128];
    tmp[tid] = acc;
    __syncthreads();
    if (tid < 32) {
        const float4 t0 = tmp[tid],      t1 = tmp[tid + 32];
        const float4 t2 = tmp[tid + 64], t3 = tmp[tid + 96];
        float4 r;
        r.x = ((t0.x + t1.x) + (t2.x + t3.x)) * inv;
        r.y = ((t0.y + t1.y) + (t2.y + t3.y)) * inv;
        r.z = ((t0.z + t1.z) + (t2.z + t3.z)) * inv;
        r.w = ((t0.w + t1.w) + (t2.w + t3.w)) * inv;
        ((float4*)(out + CTX_OFF + (size_t)b * CD))[role * 32 + tid] = r;
    }
}

extern "C" void kernel_launch(void* const* d_in, const int* in_sizes, int n_in,
                              void* d_out, int out_size)
{
    const float* query  = (const float*)d_in[0];  // [B,1,QD]
    const float* inputs = (const float*)d_in[1];  // [B,T,CD]
    const float* alpha  = (const float*)d_in[2];  // [B,T]
    const float* u      = (const float*)d_in[3];  // [B,1]
    const float* sq     = (const float*)d_in[4];  // [B,1]
    const float* W_u    = (const float*)d_in[5];  // [QD+CD,1]
    const float* b_u    = (const float*)d_in[6];  // [1]
    const float* W_sq   = (const float*)d_in[7];  // [QD+CD,1]
    const float* b_sq   = (const float*)d_in[8];  // [1]
    float* out = (float*)d_out;

    float* partial;
    float* hdot;
    unsigned int* cnt;
    unsigned int* done;
    cudaGetSymbolAddress((void**)&partial, g_partial);
    cudaGetSymbolAddress((void**)&hdot, g_hdot);
    cudaGetSymbolAddress((void**)&cnt, g_cnt);
    cudaGetSymbolAddress((void**)&done, g_done);

    dim3 g2(SPLITS, BB);
    k_context_partial<<<g2, 128>>>(inputs, alpha, u, sq, W_u, W_sq,
                                   partial, hdot, cnt);

    // PDL secondary: becomes resident once all K2 blocks have started
    // (trigger at K2 block entry); per-batch ordering via acquire/release.
    cudaLaunchConfig_t cfg = {};
    cfg.gridDim  = dim3(6, BB, 1);
    cfg.blockDim = dim3(128, 1, 1);
    cfg.dynamicSmemBytes = 0;
    cfg.stream = 0;
    cudaLaunchAttribute attrs[1];
    attrs[0].id = cudaLaunchAttributeProgrammaticStreamSerialization;
    attrs[0].val.programmaticStreamSerializationAllowed = 1;
    cfg.attrs = attrs;
    cfg.numAttrs = 1;

    cudaLaunchKernelEx(&cfg, k_finish,
                       (const float*)partial, (const float*)hdot,
                       alpha, u, sq, query,
                       W_u, b_u, W_sq, b_sq, out, cnt, done);
}

// round 10
// speedup vs baseline: 1.0750x; 1.0750x over previous
#include <cuda_runtime.h>
#include <cuda_bf16.h>
#include <math.h>

// Problem constants
#define BB 64
#define TT 1024
#define QD 1024
#define CD 512
#define NT 256          // threads per block
#define NCB 8           // column blocks per batch
#define CBW 64          // columns per block (CD / NCB)
#define NSL 16          // t-slices per block
#define SLT 64          // t per slice (TT / NSL)

// Output layout (float32): context[B,CD] | a[B,T] | u_new[B] | sq_new[B]
#define CTX_OFF 0
#define A_OFF   (BB * CD)                 // 32768
#define U_OFF   (A_OFF + BB * TT)         // 98304
#define SQ_OFF  (U_OFF + BB)              // 98368

// Cross-block scratch: per (batch, col-block) head-dot pair + ticket counters.
__device__ float        g_hdot[BB * NCB * 2];
__device__ unsigned int g_cnt[BB];           // zero-init; reducer resets

__device__ __forceinline__ float alpha_v(
    const float* __restrict__ arow, int t, float ub, float sqb)
{
    const float cur  = arow[t];
    const float prev = (t > 0) ? arow[t - 1] : 0.0f;
    const float base = fmaf(-ub, cur, cur) + fmaf(ub, prev, 1e-6f);
    return __expf(sqb * __logf(base));   // base > 0 always
}

// ---------------------------------------------------------------------------
// Single kernel. Grid (NCB, B), NT threads.
// Each block owns 64 context columns across ALL 1024 timesteps:
//   1. compute all v[t] (identical order in every block -> identical S),
//   2. stream its 64-column slab of inputs (float4, __ldcs), accumulate,
//   3. write FINAL normalized context columns (no cross-block reduction),
//   4. publish a 2-scalar head-dot contribution; last-of-8 block per batch
//      finishes the sigmoid heads (tiny tail, overlapped with other batches).
// Block cb==0 also writes the normalized 'a' row.
// ---------------------------------------------------------------------------
__global__ void __launch_bounds__(NT) k_all(
    const float* __restrict__ inputs,
    const float* __restrict__ alpha,
    const float* __restrict__ u,
    const float* __restrict__ sq,
    const float* __restrict__ query,
    const float* __restrict__ W_u,  const float* __restrict__ b_u,
    const float* __restrict__ W_sq, const float* __restrict__ b_sq,
    float* __restrict__ out,
    float* __restrict__ hdot,
    unsigned int* __restrict__ cnt)
{
    const int cb  = blockIdx.x;     // column block 0..7
    const int b   = blockIdx.y;
    const int tid = threadIdx.x;
    const int lane = tid & 31;
    const int wid  = tid >> 5;

    __shared__ float  sa[TT];            // v values for all t
    __shared__ float4 part[NSL * 16];    // [slice][group] partial accumulators
    __shared__ float  red[8];
    __shared__ float  hus[16], hss[16];
    __shared__ unsigned int tk;

    // --- v[t] for all t, and S (identical order in every block) ---
    const float ub  = u[b];
    const float sqb = sq[b];
    const float* arow = alpha + (size_t)b * TT;
    float sacc = 0.0f;
    #pragma unroll
    for (int k = 0; k < TT / NT; k++) {
        const int t = tid + k * NT;
        const float v = alpha_v(arow, t, ub, sqb);
        sa[t] = v;
        sacc += v;
    }
    #pragma unroll
    for (int o = 16; o > 0; o >>= 1) sacc += __shfl_xor_sync(0xffffffffu, sacc, o);
    if (lane == 0) red[wid] = sacc;
    __syncthreads();
    const float S = ((red[0] + red[1]) + (red[2] + red[3]))
                  + ((red[4] + red[5]) + (red[6] + red[7]));
    const float inv = 1.0f / S;

    // --- normalized 'a' row (block cb==0 only) ---
    if (cb == 0) {
        #pragma unroll
        for (int k = 0; k < TT / NT; k++) {
            const int t = tid + k * NT;
            out[A_OFF + (size_t)b * TT + t] = sa[t] * inv;
        }
    }

    // --- streaming matvec over this block's 64-column slab ---
    const int g  = tid & 15;            // float4 group within slab (16 groups)
    const int sl = tid >> 4;            // t-slice 0..15
    const float4* __restrict__ inp =
        (const float4*)(inputs + ((size_t)b * TT + sl * SLT) * CD + cb * CBW) + g;
    const float* __restrict__ w = sa + sl * SLT;

    float4 a0 = {0,0,0,0}, a1 = {0,0,0,0}, a2 = {0,0,0,0}, a3 = {0,0,0,0};
    #pragma unroll 4
    for (int i = 0; i < SLT; i += 4) {
        const float4 v0 = __ldcs(&inp[(size_t)(i + 0) * (CD/4)]);
        const float4 v1 = __ldcs(&inp[(size_t)(i + 1) * (CD/4)]);
        const float4 v2 = __ldcs(&inp[(size_t)(i + 2) * (CD/4)]);
        const float4 v3 = __ldcs(&inp[(size_t)(i + 3) * (CD/4)]);
        const float w0 = w[i + 0], w1 = w[i + 1], w2 = w[i + 2], w3 = w[i + 3];
        a0.x = fmaf(w0, v0.x, a0.x); a0.y = fmaf(w0, v0.y, a0.y);
        a0.z = fmaf(w0, v0.z, a0.z); a0.w = fmaf(w0, v0.w, a0.w);
        a1.x = fmaf(w1, v1.x, a1.x); a1.y = fmaf(w1, v1.y, a1.y);
        a1.z = fmaf(w1, v1.z, a1.z); a1.w = fmaf(w1, v1.w, a1.w);
        a2.x = fmaf(w2, v2.x, a2.x); a2.y = fmaf(w2, v2.y, a2.y);
        a2.z = fmaf(w2, v2.z, a2.z); a2.w = fmaf(w2, v2.w, a2.w);
        a3.x = fmaf(w3, v3.x, a3.x); a3.y = fmaf(w3, v3.y, a3.y);
        a3.z = fmaf(w3, v3.z, a3.z); a3.w = fmaf(w3, v3.w, a3.w);
    }
    float4 acc;
    acc.x = (a0.x + a1.x) + (a2.x + a3.x);
    acc.y = (a0.y + a1.y) + (a2.y + a3.y);
    acc.z = (a0.z + a1.z) + (a2.z + a3.z);
    acc.w = (a0.w + a1.w) + (a2.w + a3.w);
    part[sl * 16 + g] = acc;
    __syncthreads();

    // --- finalize: threads 0..15 fold the 16 slices, write normalized ctx ---
    if (tid < 16) {
        float4 c = {0,0,0,0};
        #pragma unroll
        for (int s = 0; s < NSL; s++) {
            const float4 p = part[s * 16 + tid];
            c.x += p.x; c.y += p.y; c.z += p.z; c.w += p.w;
        }
        c.x *= inv; c.y *= inv; c.z *= inv; c.w *= inv;
        ((float4*)(out + CTX_OFF + (size_t)b * CD + cb * CBW))[tid] = c;

        // head-dot contribution of these 4 columns
        const float4 wu = ((const float4*)(W_u  + cb * CBW))[tid];
        const float4 ws = ((const float4*)(W_sq + cb * CBW))[tid];
        hus[tid] = c.x * wu.x + c.y * wu.y + c.z * wu.z + c.w * wu.w;
        hss[tid] = c.x * ws.x + c.y * ws.y + c.z * ws.z + c.w * ws.w;
    }
    __syncthreads();

    // --- publish head-dot pair (tid 0 owns the cross-block write) ---
    if (tid == 0) {
        float hu = 0.0f, hs = 0.0f;
        #pragma unroll
        for (int i = 0; i < 16; i++) { hu += hus[i]; hs += hss[i]; }
        hdot[((size_t)b * NCB + cb) * 2 + 0] = hu;
        hdot[((size_t)b * NCB + cb) * 2 + 1] = hs;
        __threadfence();                      // order hdot before ticket
        tk = atomicAdd(&cnt[b], 1u);
    }
    __syncthreads();
    if (tk != NCB - 1) return;

    // ====================== tail: heads for batch b =========================
    if (tid == 0) cnt[b] = 0u;                // replay-safe reset

    // query-part dot: 1024 floats = 256 float4, one per thread
    const float4 q  = ((const float4*)(query + (size_t)b * QD))[tid];
    const float4 wu = ((const float4*)(W_u  + CD))[tid];
    const float4 ws = ((const float4*)(W_sq + CD))[tid];
    float pu = q.x * wu.x + q.y * wu.y + q.z * wu.z + q.w * wu.w;
    float ps = q.x * ws.x + q.y * ws.y + q.z * ws.z + q.w * ws.w;
    #pragma unroll
    for (int o = 16; o > 0; o >>= 1) {
        pu += __shfl_xor_sync(0xffffffffu, pu, o);
        ps += __shfl_xor_sync(0xffffffffu, ps, o);
    }
    __shared__ float ru[8], rs[8];
    if (lane == 0) { ru[wid] = pu; rs[wid] = ps; }
    __syncthreads();

    if (tid == 0) {
        __threadfence();                      // acquire peers' hdot writes
        float hu = 0.0f, hs = 0.0f;
        #pragma unroll
        for (int k = 0; k < NCB; k++) {
            hu += hdot[((size_t)b * NCB + k) * 2 + 0];
            hs += hdot[((size_t)b * NCB + k) * 2 + 1];
        }
        const float QU = ((ru[0] + ru[1]) + (ru[2] + ru[3]))
                       + ((ru[4] + ru[5]) + (ru[6] + ru[7]));
        const float QS = ((rs[0] + rs[1]) + (rs[2] + rs[3]))
                       + ((rs[4] + rs[5]) + (rs[6] + rs[7]));
        const float PU = hu + QU + b_u[0];
        const float PS = hs + QS + b_sq[0];
        out[U_OFF + b]  = 1.0f / (1.0f + expf(-PU));
        out[SQ_OFF + b] = 1.0f / (1.0f + expf(-PS)) + 1.0f;
    }
}

extern "C" void kernel_launch(void* const* d_in, const int* in_sizes, int n_in,
                              void* d_out, int out_size)
{
    const float* query  = (const float*)d_in[0];  // [B,1,QD]
    const float* inputs = (const float*)d_in[1];  // [B,T,CD]
    const float* alpha  = (const float*)d_in[2];  // [B,T]
    const float* u      = (const float*)d_in[3];  // [B,1]
    const float* sq     = (const float*)d_in[4];  // [B,1]
    const float* W_u    = (const float*)d_in[5];  // [QD+CD,1]
    const float* b_u    = (const float*)d_in[6];  // [1]
    const float* W_sq   = (const float*)d_in[7];  // [QD+CD,1]
    const float* b_sq   = (const float*)d_in[8];  // [1]
    float* out = (float*)d_out;

    float* hdot;
    unsigned int* cnt;
    cudaGetSymbolAddress((void**)&hdot, g_hdot);
    cudaGetSymbolAddress((void**)&cnt, g_cnt);

    dim3 g(NCB, BB);
    k_all<<<g, NT>>>(inputs, alpha, u, sq, query,
                     W_u, b_u, W_sq, b_sq, out, hdot, cnt);
}